// round 13
// baseline (speedup 1.0000x reference)
#include <cuda_runtime.h>

// Problem-shape maxima (compile-time array sizing; runtime uses in_sizes)
#define N1MAX 50000
#define NPMAX 200000
#define NTOTMAX (N1MAX + 2 * NPMAX)        // unified count/offset domain: 450000
#define E1MAX 1600000
#define E2MAX 1600000
#define SLOTMAX (E1MAX + 2 * E2MAX)        // 4.8M CSR slots
#define H2 32

// ---------------- scratch (static __device__, no allocation) ----------------
__device__ int   g_cnt [NTOTMAX];    // [0,n1): conv1 dst deg | [n1,n1+np): conv2a | [n1+np,..): conv2b
__device__ int   g_off [NTOTMAX];    // exclusive-scan starts (stable)
__device__ int   g_head[NTOTMAX];    // fill cursors; after fill = region ends
__device__ int   g_bsum [512];
__device__ int   g_bsum2[512];
__device__ int   g_slot[SLOTMAX];    // CSR: src indices bucketed by dst
__device__ float g_dinv1[N1MAX];
__device__ float g_dinvf[NPMAX];
__device__ float g_dinvb[NPMAX];
__device__ __align__(16) float g_y1  [N1MAX * H2];   // xw1 * dinv1[src]
__device__ __align__(16) float g_out1[N1MAX * H2];   // raw acc: y1[d] + sum y1[src]
__device__ __align__(16) float g_ya  [NPMAX * H2];
__device__ __align__(16) float g_yb  [NPMAX * H2];
__device__ __align__(16) float g_outa[NPMAX * H2];
__device__ __align__(16) float g_outb[NPMAX * H2];

// ---------------- 1. zero unified degree counters ----------------
__global__ void k_zero(int ntot) {
    int i = blockIdx.x * blockDim.x + threadIdx.x;
    if (i < ntot) g_cnt[i] = 0;
}

// ---------------- 2. degree counting (all three graphs, unified) -----------
__global__ void k_count(const int* __restrict__ e1, const int* __restrict__ e2,
                        int E1, int E2, int base_f, int base_b) {
    int i = blockIdx.x * blockDim.x + threadIdx.x;
    if (i < E1) atomicAdd(&g_cnt[e1[E1 + i]], 1);               // conv1 dst = edge1[1]
    if (i < E2) {
        atomicAdd(&g_cnt[base_f + e2[E2 + i]], 1);              // conv2a dst = ei2[1]
        atomicAdd(&g_cnt[base_b + e2[i]],      1);              // conv2b dst = ei2[0]
    }
}

// ---------------- 3. exclusive scan, 3 phases (1024 items / block) ----------
__global__ __launch_bounds__(256) void k_scanA(int ntot) {
    __shared__ int sh[256];
    int tid = threadIdx.x;
    int base = blockIdx.x * 1024 + tid * 4;
    int v0 = 0, v1 = 0, v2 = 0, v3 = 0;
    if (base + 0 < ntot) v0 = g_cnt[base + 0];
    if (base + 1 < ntot) v1 = g_cnt[base + 1];
    if (base + 2 < ntot) v2 = g_cnt[base + 2];
    if (base + 3 < ntot) v3 = g_cnt[base + 3];
    int tot = v0 + v1 + v2 + v3;
    sh[tid] = tot;
    __syncthreads();
    #pragma unroll
    for (int d = 1; d < 256; d <<= 1) {
        int t = (tid >= d) ? sh[tid - d] : 0;
        __syncthreads();
        sh[tid] += t;
        __syncthreads();
    }
    int excl = sh[tid] - tot;
    if (tid == 255) g_bsum[blockIdx.x] = sh[255];
    if (base + 0 < ntot) g_off[base + 0] = excl;
    if (base + 1 < ntot) g_off[base + 1] = excl + v0;
    if (base + 2 < ntot) g_off[base + 2] = excl + v0 + v1;
    if (base + 3 < ntot) g_off[base + 3] = excl + v0 + v1 + v2;
}

__global__ __launch_bounds__(512) void k_scanB(int nblk) {
    __shared__ int sh[512];
    int tid = threadIdx.x;
    int v = (tid < nblk) ? g_bsum[tid] : 0;
    sh[tid] = v;
    __syncthreads();
    #pragma unroll
    for (int d = 1; d < 512; d <<= 1) {
        int t = (tid >= d) ? sh[tid - d] : 0;
        __syncthreads();
        sh[tid] += t;
        __syncthreads();
    }
    if (tid < nblk) g_bsum2[tid] = sh[tid] - v;
}

__global__ void k_scanC(int ntot) {
    int i = blockIdx.x * blockDim.x + threadIdx.x;
    if (i < ntot) {
        int val = g_off[i] + g_bsum2[i >> 10];
        g_off[i]  = val;
        g_head[i] = val;
    }
}

// ---------------- 4. rsqrt degrees ONCE (deg = count + 1 self-loop) ---------
__global__ void k_dinv(int n1, int np, int base_f, int base_b) {
    int i = blockIdx.x * blockDim.x + threadIdx.x;
    if (i < np) {
        g_dinvf[i] = rsqrtf((float)(g_cnt[base_f + i] + 1));
        g_dinvb[i] = rsqrtf((float)(g_cnt[base_b + i] + 1));
    }
    if (i < n1) g_dinv1[i] = rsqrtf((float)(g_cnt[i] + 1));
}

// ---------------- 5. CSR fill: bucket src indices by dst --------------------
__global__ void k_fill(const int* __restrict__ e1, const int* __restrict__ e2,
                       int E1, int E2, int base_f, int base_b) {
    int i = blockIdx.x * blockDim.x + threadIdx.x;
    if (i < E1) {
        int s = e1[i], d = e1[E1 + i];
        g_slot[atomicAdd(&g_head[d], 1)] = s;
    }
    if (i < E2) {
        int u = e2[i], v = e2[E2 + i];
        g_slot[atomicAdd(&g_head[base_f + v], 1)] = u;   // conv2a: u -> v
        g_slot[atomicAdd(&g_head[base_b + u], 1)] = v;   // conv2b: v -> u
    }
}

// ---------------- 6. embed gather + register-tiled GEMM (256 -> 32) ---------
__global__ __launch_bounds__(256) void k_embed(
    const int* __restrict__ x, const float* __restrict__ emb,
    const float* __restrict__ W1, int n1)
{
    __shared__ __align__(16) float Ws[64 * 32];       // 8 KB (per-chunk W)
    __shared__ __align__(16) float As[128 * 68];      // 34 KB, row stride 68

    int tid = threadIdx.x;
    int c4 = tid & 7;
    int ty = (tid >> 3) & 7;
    int st = tid >> 6;
    int nodeBase = blockIdx.x * 128;

    float acc[4][4];
    #pragma unroll
    for (int m = 0; m < 4; m++)
        #pragma unroll
        for (int c = 0; c < 4; c++) acc[m][c] = 0.f;

    int lcol = tid & 15;
    int lrow = tid >> 4;

    for (int ch = 0; ch < 4; ch++) {
        #pragma unroll
        for (int i = 0; i < 8; i++)
            Ws[i * 256 + tid] = W1[ch * 2048 + i * 256 + tid];
        #pragma unroll
        for (int pass = 0; pass < 8; pass++) {
            int r = lrow + pass * 16;
            int n = nodeBase + r;
            if (n < n1) {
                int xi = x[n];
                float4 v = reinterpret_cast<const float4*>(emb)
                               [(size_t)xi * 64 + ch * 16 + lcol];
                *reinterpret_cast<float4*>(&As[r * 68 + lcol * 4]) = v;
            }
        }
        __syncthreads();

        #pragma unroll
        for (int k4 = 0; k4 < 16; k4++) {
            float4 w0 = *reinterpret_cast<const float4*>(&Ws[(k4 * 4 + 0) * 32 + c4 * 4]);
            float4 w1 = *reinterpret_cast<const float4*>(&Ws[(k4 * 4 + 1) * 32 + c4 * 4]);
            float4 w2 = *reinterpret_cast<const float4*>(&Ws[(k4 * 4 + 2) * 32 + c4 * 4]);
            float4 w3 = *reinterpret_cast<const float4*>(&Ws[(k4 * 4 + 3) * 32 + c4 * 4]);
            #pragma unroll
            for (int m = 0; m < 4; m++) {
                int row = st * 32 + ty + 8 * m;
                float4 a = *reinterpret_cast<const float4*>(&As[row * 68 + k4 * 4]);
                acc[m][0] += a.x * w0.x + a.y * w1.x + a.z * w2.x + a.w * w3.x;
                acc[m][1] += a.x * w0.y + a.y * w1.y + a.z * w2.y + a.w * w3.y;
                acc[m][2] += a.x * w0.z + a.y * w1.z + a.z * w2.z + a.w * w3.z;
                acc[m][3] += a.x * w0.w + a.y * w1.w + a.z * w2.w + a.w * w3.w;
            }
        }
        __syncthreads();
    }

    #pragma unroll
    for (int m = 0; m < 4; m++) {
        int node = nodeBase + st * 32 + ty + 8 * m;
        if (node < n1) {
            float dv = g_dinv1[node];
            float4 y = make_float4(acc[m][0] * dv, acc[m][1] * dv,
                                   acc[m][2] * dv, acc[m][3] * dv);
            *reinterpret_cast<float4*>(&g_y1[node * 32 + c4 * 4]) = y;
        }
    }
}

// ---------------- 7. conv1 CSR gather: no atomics ---------------------------
// out1[n] = y1[n] + sum_{s in bucket(n)} y1[s]   (raw; dinv+bias deferred)
__global__ void k_gather1(int n1) {
    int tid = blockIdx.x * 256 + threadIdx.x;
    int n = tid >> 3, t = tid & 7;
    if (n >= n1) return;
    int j = g_off[n], e = g_head[n];
    float4 acc = *reinterpret_cast<const float4*>(&g_y1[n * 32 + t * 4]);
    for (; j + 2 <= e; j += 2) {
        int s0 = g_slot[j], s1 = g_slot[j + 1];
        float4 a = *reinterpret_cast<const float4*>(&g_y1[s0 * 32 + t * 4]);
        float4 b = *reinterpret_cast<const float4*>(&g_y1[s1 * 32 + t * 4]);
        acc.x += a.x + b.x; acc.y += a.y + b.y;
        acc.z += a.z + b.z; acc.w += a.w + b.w;
    }
    if (j < e) {
        int s = g_slot[j];
        float4 a = *reinterpret_cast<const float4*>(&g_y1[s * 32 + t * 4]);
        acc.x += a.x; acc.y += a.y; acc.z += a.z; acc.w += a.w;
    }
    *reinterpret_cast<float4*>(&g_out1[n * 32 + t * 4]) = acc;
}

// ---------------- 8. pair gather-multiply + fused 32x32 GEMVs ---------------
// Applies conv1's deferred dst scaling: h = relu(acc * dinv1 + b1).
__global__ __launch_bounds__(256) void k_pair(
    const int* __restrict__ pos,
    const float* __restrict__ W2a, const float* __restrict__ b1v,
    const float* __restrict__ W2b, int np)
{
    __shared__ __align__(16) float Was[1024];
    __shared__ __align__(16) float Wbs[1024];
    int tid = threadIdx.x;
    for (int i = tid; i < 1024; i += 256) { Was[i] = W2a[i]; Wbs[i] = W2b[i]; }
    __syncthreads();

    int g = blockIdx.x * 256 + tid;
    int m = g >> 3, t = g & 7;
    bool ok = (m < np);
    int p0 = 0, p1 = 0;
    if (ok) { p0 = pos[2 * m]; p1 = pos[2 * m + 1]; }

    float dv0 = g_dinv1[p0], dv1 = g_dinv1[p1];
    float4 b14 = *reinterpret_cast<const float4*>(&b1v[t * 4]);
    float4 h0 = *reinterpret_cast<const float4*>(&g_out1[p0 * 32 + t * 4]);
    float4 h1 = *reinterpret_cast<const float4*>(&g_out1[p1 * 32 + t * 4]);
    float4 hp;
    hp.x = fmaxf(h0.x * dv0 + b14.x, 0.f) * fmaxf(h1.x * dv1 + b14.x, 0.f);
    hp.y = fmaxf(h0.y * dv0 + b14.y, 0.f) * fmaxf(h1.y * dv1 + b14.y, 0.f);
    hp.z = fmaxf(h0.z * dv0 + b14.z, 0.f) * fmaxf(h1.z * dv1 + b14.z, 0.f);
    hp.w = fmaxf(h0.w * dv0 + b14.w, 0.f) * fmaxf(h1.w * dv1 + b14.w, 0.f);

    float4 aa = make_float4(0.f, 0.f, 0.f, 0.f);
    float4 ab = make_float4(0.f, 0.f, 0.f, 0.f);
    #pragma unroll
    for (int src = 0; src < 8; src++) {
        float hv[4];
        hv[0] = __shfl_sync(0xffffffffu, hp.x, src, 8);
        hv[1] = __shfl_sync(0xffffffffu, hp.y, src, 8);
        hv[2] = __shfl_sync(0xffffffffu, hp.z, src, 8);
        hv[3] = __shfl_sync(0xffffffffu, hp.w, src, 8);
        #pragma unroll
        for (int kk = 0; kk < 4; kk++) {
            int k = src * 4 + kk;
            float4 wa = *reinterpret_cast<const float4*>(&Was[k * 32 + t * 4]);
            float4 wb = *reinterpret_cast<const float4*>(&Wbs[k * 32 + t * 4]);
            aa.x += hv[kk] * wa.x; aa.y += hv[kk] * wa.y;
            aa.z += hv[kk] * wa.z; aa.w += hv[kk] * wa.w;
            ab.x += hv[kk] * wb.x; ab.y += hv[kk] * wb.y;
            ab.z += hv[kk] * wb.z; ab.w += hv[kk] * wb.w;
        }
    }

    if (ok) {
        float da = g_dinvf[m], db = g_dinvb[m];
        *reinterpret_cast<float4*>(&g_ya[m * 32 + t * 4]) =
            make_float4(aa.x * da, aa.y * da, aa.z * da, aa.w * da);
        *reinterpret_cast<float4*>(&g_yb[m * 32 + t * 4]) =
            make_float4(ab.x * db, ab.y * db, ab.z * db, ab.w * db);
    }
}

// ---------------- 9. conv2 CSR gather (fwd + reversed): no atomics ----------
__global__ void k_gather2(int np, int base_f, int base_b) {
    int tid = blockIdx.x * 256 + threadIdx.x;
    int m = tid >> 3, t = tid & 7;
    if (m >= np) return;

    // conv2a: dst m, srcs in f-bucket
    int j = g_off[base_f + m], e = g_head[base_f + m];
    float4 acc = *reinterpret_cast<const float4*>(&g_ya[m * 32 + t * 4]);
    for (; j + 2 <= e; j += 2) {
        int s0 = g_slot[j], s1 = g_slot[j + 1];
        float4 a = *reinterpret_cast<const float4*>(&g_ya[s0 * 32 + t * 4]);
        float4 b = *reinterpret_cast<const float4*>(&g_ya[s1 * 32 + t * 4]);
        acc.x += a.x + b.x; acc.y += a.y + b.y;
        acc.z += a.z + b.z; acc.w += a.w + b.w;
    }
    if (j < e) {
        int s = g_slot[j];
        float4 a = *reinterpret_cast<const float4*>(&g_ya[s * 32 + t * 4]);
        acc.x += a.x; acc.y += a.y; acc.z += a.z; acc.w += a.w;
    }
    *reinterpret_cast<float4*>(&g_outa[m * 32 + t * 4]) = acc;

    // conv2b: dst m, srcs in b-bucket
    j = g_off[base_b + m]; e = g_head[base_b + m];
    acc = *reinterpret_cast<const float4*>(&g_yb[m * 32 + t * 4]);
    for (; j + 2 <= e; j += 2) {
        int s0 = g_slot[j], s1 = g_slot[j + 1];
        float4 a = *reinterpret_cast<const float4*>(&g_yb[s0 * 32 + t * 4]);
        float4 b = *reinterpret_cast<const float4*>(&g_yb[s1 * 32 + t * 4]);
        acc.x += a.x + b.x; acc.y += a.y + b.y;
        acc.z += a.z + b.z; acc.w += a.w + b.w;
    }
    if (j < e) {
        int s = g_slot[j];
        float4 a = *reinterpret_cast<const float4*>(&g_yb[s * 32 + t * 4]);
        acc.x += a.x; acc.y += a.y; acc.z += a.z; acc.w += a.w;
    }
    *reinterpret_cast<float4*>(&g_outb[m * 32 + t * 4]) = acc;
}

// ---------------- 10. final: deferred conv2 scaling + even*odd + dot Wp -----
__global__ void k_final(const int* __restrict__ idx,
                        const float* __restrict__ b2a, const float* __restrict__ b2b,
                        const float* __restrict__ Wp, const float* __restrict__ bp,
                        float* __restrict__ out, int Q)
{
    int tid = blockIdx.x * 256 + threadIdx.x;
    int q = tid >> 3, t = tid & 7;
    bool ok = (q < Q);
    int i0 = 0, i1 = 0;
    if (ok) { i0 = idx[2 * q]; i1 = idx[2 * q + 1]; }

    float f0 = g_dinvf[i0], g0 = g_dinvb[i0];
    float f1 = g_dinvf[i1], g1 = g_dinvb[i1];
    float4 ba = *reinterpret_cast<const float4*>(&b2a[t * 4]);
    float4 bb = *reinterpret_cast<const float4*>(&b2b[t * 4]);

    float4 a0 = *reinterpret_cast<const float4*>(&g_outa[i0 * 32 + t * 4]);
    float4 c0 = *reinterpret_cast<const float4*>(&g_outb[i0 * 32 + t * 4]);
    float4 a1 = *reinterpret_cast<const float4*>(&g_outa[i1 * 32 + t * 4]);
    float4 c1 = *reinterpret_cast<const float4*>(&g_outb[i1 * 32 + t * 4]);

    float4 h0, h1;
    h0.x = fmaxf(a0.x * f0 + ba.x, 0.f) + fmaxf(c0.x * g0 + bb.x, 0.f);
    h0.y = fmaxf(a0.y * f0 + ba.y, 0.f) + fmaxf(c0.y * g0 + bb.y, 0.f);
    h0.z = fmaxf(a0.z * f0 + ba.z, 0.f) + fmaxf(c0.z * g0 + bb.z, 0.f);
    h0.w = fmaxf(a0.w * f0 + ba.w, 0.f) + fmaxf(c0.w * g0 + bb.w, 0.f);
    h1.x = fmaxf(a1.x * f1 + ba.x, 0.f) + fmaxf(c1.x * g1 + bb.x, 0.f);
    h1.y = fmaxf(a1.y * f1 + ba.y, 0.f) + fmaxf(c1.y * g1 + bb.y, 0.f);
    h1.z = fmaxf(a1.z * f1 + ba.z, 0.f) + fmaxf(c1.z * g1 + bb.z, 0.f);
    h1.w = fmaxf(a1.w * f1 + ba.w, 0.f) + fmaxf(c1.w * g1 + bb.w, 0.f);

    float4 wp4 = *reinterpret_cast<const float4*>(&Wp[t * 4]);
    float s = h0.x * h1.x * wp4.x + h0.y * h1.y * wp4.y
            + h0.z * h1.z * wp4.z + h0.w * h1.w * wp4.w;
    s += __shfl_xor_sync(0xffffffffu, s, 1, 8);
    s += __shfl_xor_sync(0xffffffffu, s, 2, 8);
    s += __shfl_xor_sync(0xffffffffu, s, 4, 8);
    if (ok && t == 0) out[q] = s + __ldg(bp);
}

// ---------------- launch ----------------------------------------------------
extern "C" void kernel_launch(void* const* d_in, const int* in_sizes, int n_in,
                              void* d_out, int out_size) {
    const int*   x    = (const int*)  d_in[0];
    const int*   e1   = (const int*)  d_in[1];
    const int*   pos  = (const int*)  d_in[2];
    const int*   idx  = (const int*)  d_in[3];
    const int*   e2   = (const int*)  d_in[4];
    const float* emb  = (const float*)d_in[5];
    const float* W1   = (const float*)d_in[6];
    const float* b1   = (const float*)d_in[7];
    const float* b2a  = (const float*)d_in[9];
    const float* W2a  = (const float*)d_in[8];
    const float* W2b  = (const float*)d_in[10];
    const float* b2b  = (const float*)d_in[11];
    const float* Wp   = (const float*)d_in[12];
    const float* bp   = (const float*)d_in[13];
    float* out = (float*)d_out;

    int n1 = in_sizes[0];
    int E1 = in_sizes[1] / 2;
    int np = in_sizes[2] / 2;
    int Q  = in_sizes[3] / 2;
    int E2 = in_sizes[4] / 2;

    int base_f = n1;
    int base_b = n1 + np;
    int ntot   = n1 + 2 * np;
    int nblk   = (ntot + 1023) / 1024;
    int mx = (np > n1) ? np : n1;
    int Em = (E1 > E2) ? E1 : E2;

    k_zero   <<<(ntot + 255) / 256, 256>>>(ntot);
    k_count  <<<(Em + 255) / 256, 256>>>(e1, e2, E1, E2, base_f, base_b);
    k_scanA  <<<nblk, 256>>>(ntot);
    k_scanB  <<<1, 512>>>(nblk);
    k_scanC  <<<(ntot + 255) / 256, 256>>>(ntot);
    k_dinv   <<<(mx + 255) / 256, 256>>>(n1, np, base_f, base_b);
    k_fill   <<<(Em + 255) / 256, 256>>>(e1, e2, E1, E2, base_f, base_b);
    k_embed  <<<(n1 + 127) / 128, 256>>>(x, emb, W1, n1);
    k_gather1<<<(int)(((long long)n1 * 8 + 255) / 256), 256>>>(n1);
    k_pair   <<<(int)(((long long)np * 8 + 255) / 256), 256>>>(pos, W2a, b1, W2b, np);
    k_gather2<<<(int)(((long long)np * 8 + 255) / 256), 256>>>(np, base_f, base_b);
    k_final  <<<(int)(((long long)Q  * 8 + 255) / 256), 256>>>(idx, b2a, b2b, Wp, bp, out, Q);
}

// round 14
// speedup vs baseline: 1.0304x; 1.0304x over previous
#include <cuda_runtime.h>

// Problem-shape maxima (compile-time array sizing; runtime uses in_sizes)
#define N1MAX 50000
#define NPMAX 200000
#define NTOTMAX (N1MAX + 2 * NPMAX)        // scan domain: src1 | u | v
#define E1MAX 1600000
#define E2MAX 1600000
#define SLOTMAX (E1MAX + 2 * E2MAX)        // 4.8M (src,dst) slots
#define H2 32

// ---------------- scratch (static __device__, no allocation) ----------------
__device__ int   g_cnt [NTOTMAX];    // src-degree counts: [0,n1) e1-src | [n1,n1+np) ei2[0] | [n1+np,..) ei2[1]
__device__ int   g_cntd[N1MAX];      // conv1 dst-degree counts (for dinv1 only)
__device__ int   g_off [NTOTMAX];    // exclusive-scan slot starts
__device__ int   g_head[NTOTMAX];    // fill cursors
__device__ int   g_bsum [512];
__device__ int   g_bsum2[512];
__device__ int2  g_slot2[SLOTMAX];   // (src,dst) pairs, bucketed (sorted) by src
__device__ float g_dinv1[N1MAX];
__device__ float g_dinvf[NPMAX];
__device__ float g_dinvb[NPMAX];
__device__ __align__(16) float g_y1  [N1MAX * H2];   // xw1 * dinv1[src]
__device__ __align__(16) float g_out1[N1MAX * H2];   // raw acc: y1[d] + sum y1[src]
__device__ __align__(16) float g_ya  [NPMAX * H2];
__device__ __align__(16) float g_yb  [NPMAX * H2];
__device__ __align__(16) float g_outa[NPMAX * H2];
__device__ __align__(16) float g_outb[NPMAX * H2];

__device__ __forceinline__ void red_add_v4(float* addr, float4 v) {
    asm volatile("red.global.add.v4.f32 [%0], {%1,%2,%3,%4};"
                 :: "l"(addr), "f"(v.x), "f"(v.y), "f"(v.z), "f"(v.w)
                 : "memory");
}

// ---------------- 1. zero counters ----------------
__global__ void k_zero(int ntot, int n1) {
    int i = blockIdx.x * blockDim.x + threadIdx.x;
    if (i < ntot) g_cnt[i] = 0;
    if (i < n1)   g_cntd[i] = 0;
}

// ---------------- 2. degree counting: src degrees (buckets) + conv1 dst deg -
__global__ void k_count(const int* __restrict__ e1, const int* __restrict__ e2,
                        int E1, int E2, int base_u, int base_v) {
    int i = blockIdx.x * blockDim.x + threadIdx.x;
    if (i < E1) {
        atomicAdd(&g_cnt [e1[i]],      1);      // e1 src bucket
        atomicAdd(&g_cntd[e1[E1 + i]], 1);      // e1 dst degree (dinv1)
    }
    if (i < E2) {
        atomicAdd(&g_cnt[base_u + e2[i]],      1);   // ei2[0] bucket (conv2a src) = dinvb degree
        atomicAdd(&g_cnt[base_v + e2[E2 + i]], 1);   // ei2[1] bucket (conv2b src) = dinvf degree
    }
}

// ---------------- 3. exclusive scan, 3 phases (1024 items / block) ----------
__global__ __launch_bounds__(256) void k_scanA(int ntot) {
    __shared__ int sh[256];
    int tid = threadIdx.x;
    int base = blockIdx.x * 1024 + tid * 4;
    int v0 = 0, v1 = 0, v2 = 0, v3 = 0;
    if (base + 0 < ntot) v0 = g_cnt[base + 0];
    if (base + 1 < ntot) v1 = g_cnt[base + 1];
    if (base + 2 < ntot) v2 = g_cnt[base + 2];
    if (base + 3 < ntot) v3 = g_cnt[base + 3];
    int tot = v0 + v1 + v2 + v3;
    sh[tid] = tot;
    __syncthreads();
    #pragma unroll
    for (int d = 1; d < 256; d <<= 1) {
        int t = (tid >= d) ? sh[tid - d] : 0;
        __syncthreads();
        sh[tid] += t;
        __syncthreads();
    }
    int excl = sh[tid] - tot;
    if (tid == 255) g_bsum[blockIdx.x] = sh[255];
    if (base + 0 < ntot) g_off[base + 0] = excl;
    if (base + 1 < ntot) g_off[base + 1] = excl + v0;
    if (base + 2 < ntot) g_off[base + 2] = excl + v0 + v1;
    if (base + 3 < ntot) g_off[base + 3] = excl + v0 + v1 + v2;
}

__global__ __launch_bounds__(512) void k_scanB(int nblk) {
    __shared__ int sh[512];
    int tid = threadIdx.x;
    int v = (tid < nblk) ? g_bsum[tid] : 0;
    sh[tid] = v;
    __syncthreads();
    #pragma unroll
    for (int d = 1; d < 512; d <<= 1) {
        int t = (tid >= d) ? sh[tid - d] : 0;
        __syncthreads();
        sh[tid] += t;
        __syncthreads();
    }
    if (tid < nblk) g_bsum2[tid] = sh[tid] - v;
}

__global__ void k_scanC(int ntot) {
    int i = blockIdx.x * blockDim.x + threadIdx.x;
    if (i < ntot) {
        int val = g_off[i] + g_bsum2[i >> 10];
        g_off[i]  = val;
        g_head[i] = val;
    }
}

// ---------------- 4. rsqrt degrees ONCE (deg = count + 1 self-loop) ---------
__global__ void k_dinv(int n1, int np, int base_u, int base_v) {
    int i = blockIdx.x * blockDim.x + threadIdx.x;
    if (i < np) {
        g_dinvf[i] = rsqrtf((float)(g_cnt[base_v + i] + 1));   // deg over ei2[1]
        g_dinvb[i] = rsqrtf((float)(g_cnt[base_u + i] + 1));   // deg over ei2[0]
    }
    if (i < n1) g_dinv1[i] = rsqrtf((float)(g_cntd[i] + 1));
}

// ---------------- 5. fill: (src,dst) slots bucketed by src ------------------
__global__ void k_fill(const int* __restrict__ e1, const int* __restrict__ e2,
                       int E1, int E2, int base_u, int base_v) {
    int i = blockIdx.x * blockDim.x + threadIdx.x;
    if (i < E1) {
        int s = e1[i], d = e1[E1 + i];
        g_slot2[atomicAdd(&g_head[s], 1)] = make_int2(s, d);
    }
    if (i < E2) {
        int u = e2[i], v = e2[E2 + i];
        g_slot2[atomicAdd(&g_head[base_u + u], 1)] = make_int2(u, v);  // conv2a: ya[u] -> outa[v]
        g_slot2[atomicAdd(&g_head[base_v + v], 1)] = make_int2(v, u);  // conv2b: yb[v] -> outb[u]
    }
}

// ---------------- 6. embed gather + register-tiled GEMM (256 -> 32) ---------
__global__ __launch_bounds__(256) void k_embed(
    const int* __restrict__ x, const float* __restrict__ emb,
    const float* __restrict__ W1, int n1)
{
    __shared__ __align__(16) float Ws[64 * 32];       // 8 KB (per-chunk W)
    __shared__ __align__(16) float As[128 * 68];      // 34 KB, row stride 68

    int tid = threadIdx.x;
    int c4 = tid & 7;
    int ty = (tid >> 3) & 7;
    int st = tid >> 6;
    int nodeBase = blockIdx.x * 128;

    float acc[4][4];
    #pragma unroll
    for (int m = 0; m < 4; m++)
        #pragma unroll
        for (int c = 0; c < 4; c++) acc[m][c] = 0.f;

    int lcol = tid & 15;
    int lrow = tid >> 4;

    for (int ch = 0; ch < 4; ch++) {
        #pragma unroll
        for (int i = 0; i < 8; i++)
            Ws[i * 256 + tid] = W1[ch * 2048 + i * 256 + tid];
        #pragma unroll
        for (int pass = 0; pass < 8; pass++) {
            int r = lrow + pass * 16;
            int n = nodeBase + r;
            if (n < n1) {
                int xi = x[n];
                float4 v = reinterpret_cast<const float4*>(emb)
                               [(size_t)xi * 64 + ch * 16 + lcol];
                *reinterpret_cast<float4*>(&As[r * 68 + lcol * 4]) = v;
            }
        }
        __syncthreads();

        #pragma unroll
        for (int k4 = 0; k4 < 16; k4++) {
            float4 w0 = *reinterpret_cast<const float4*>(&Ws[(k4 * 4 + 0) * 32 + c4 * 4]);
            float4 w1 = *reinterpret_cast<const float4*>(&Ws[(k4 * 4 + 1) * 32 + c4 * 4]);
            float4 w2 = *reinterpret_cast<const float4*>(&Ws[(k4 * 4 + 2) * 32 + c4 * 4]);
            float4 w3 = *reinterpret_cast<const float4*>(&Ws[(k4 * 4 + 3) * 32 + c4 * 4]);
            #pragma unroll
            for (int m = 0; m < 4; m++) {
                int row = st * 32 + ty + 8 * m;
                float4 a = *reinterpret_cast<const float4*>(&As[row * 68 + k4 * 4]);
                acc[m][0] += a.x * w0.x + a.y * w1.x + a.z * w2.x + a.w * w3.x;
                acc[m][1] += a.x * w0.y + a.y * w1.y + a.z * w2.y + a.w * w3.y;
                acc[m][2] += a.x * w0.z + a.y * w1.z + a.z * w2.z + a.w * w3.z;
                acc[m][3] += a.x * w0.w + a.y * w1.w + a.z * w2.w + a.w * w3.w;
            }
        }
        __syncthreads();
    }

    #pragma unroll
    for (int m = 0; m < 4; m++) {
        int node = nodeBase + st * 32 + ty + 8 * m;
        if (node < n1) {
            float dv = g_dinv1[node];
            float4 y = make_float4(acc[m][0] * dv, acc[m][1] * dv,
                                   acc[m][2] * dv, acc[m][3] * dv);
            *reinterpret_cast<float4*>(&g_y1  [node * 32 + c4 * 4]) = y;
            *reinterpret_cast<float4*>(&g_out1[node * 32 + c4 * 4]) = y;  // self-loop init
        }
    }
}

// ---------------- 7. conv1 scatter, src-sorted: L1-hot reads + random REDs --
__global__ void k_scat1(int E1) {
    int tid = blockIdx.x * 256 + threadIdx.x;
    int j = tid >> 3, t = tid & 7;
    if (j >= E1) return;
    int2 sd = g_slot2[j];                      // consecutive j share sd.x (src)
    float4 y = *reinterpret_cast<const float4*>(&g_y1[sd.x * 32 + t * 4]);
    red_add_v4(&g_out1[sd.y * 32 + t * 4], y);
}

// ---------------- 8. pair gather-multiply + fused 32x32 GEMVs ---------------
// Applies conv1's deferred dst scaling: h = relu(acc * dinv1 + b1).
__global__ __launch_bounds__(256) void k_pair(
    const int* __restrict__ pos,
    const float* __restrict__ W2a, const float* __restrict__ b1v,
    const float* __restrict__ W2b, int np)
{
    __shared__ __align__(16) float Was[1024];
    __shared__ __align__(16) float Wbs[1024];
    int tid = threadIdx.x;
    for (int i = tid; i < 1024; i += 256) { Was[i] = W2a[i]; Wbs[i] = W2b[i]; }
    __syncthreads();

    int g = blockIdx.x * 256 + tid;
    int m = g >> 3, t = g & 7;
    bool ok = (m < np);
    int p0 = 0, p1 = 0;
    if (ok) { p0 = pos[2 * m]; p1 = pos[2 * m + 1]; }

    float dv0 = g_dinv1[p0], dv1 = g_dinv1[p1];
    float4 b14 = *reinterpret_cast<const float4*>(&b1v[t * 4]);
    float4 h0 = *reinterpret_cast<const float4*>(&g_out1[p0 * 32 + t * 4]);
    float4 h1 = *reinterpret_cast<const float4*>(&g_out1[p1 * 32 + t * 4]);
    float4 hp;
    hp.x = fmaxf(h0.x * dv0 + b14.x, 0.f) * fmaxf(h1.x * dv1 + b14.x, 0.f);
    hp.y = fmaxf(h0.y * dv0 + b14.y, 0.f) * fmaxf(h1.y * dv1 + b14.y, 0.f);
    hp.z = fmaxf(h0.z * dv0 + b14.z, 0.f) * fmaxf(h1.z * dv1 + b14.z, 0.f);
    hp.w = fmaxf(h0.w * dv0 + b14.w, 0.f) * fmaxf(h1.w * dv1 + b14.w, 0.f);

    float4 aa = make_float4(0.f, 0.f, 0.f, 0.f);
    float4 ab = make_float4(0.f, 0.f, 0.f, 0.f);
    #pragma unroll
    for (int src = 0; src < 8; src++) {
        float hv[4];
        hv[0] = __shfl_sync(0xffffffffu, hp.x, src, 8);
        hv[1] = __shfl_sync(0xffffffffu, hp.y, src, 8);
        hv[2] = __shfl_sync(0xffffffffu, hp.z, src, 8);
        hv[3] = __shfl_sync(0xffffffffu, hp.w, src, 8);
        #pragma unroll
        for (int kk = 0; kk < 4; kk++) {
            int k = src * 4 + kk;
            float4 wa = *reinterpret_cast<const float4*>(&Was[k * 32 + t * 4]);
            float4 wb = *reinterpret_cast<const float4*>(&Wbs[k * 32 + t * 4]);
            aa.x += hv[kk] * wa.x; aa.y += hv[kk] * wa.y;
            aa.z += hv[kk] * wa.z; aa.w += hv[kk] * wa.w;
            ab.x += hv[kk] * wb.x; ab.y += hv[kk] * wb.y;
            ab.z += hv[kk] * wb.z; ab.w += hv[kk] * wb.w;
        }
    }

    if (ok) {
        float da = g_dinvf[m], db = g_dinvb[m];
        float4 ya = make_float4(aa.x * da, aa.y * da, aa.z * da, aa.w * da);
        float4 yb = make_float4(ab.x * db, ab.y * db, ab.z * db, ab.w * db);
        *reinterpret_cast<float4*>(&g_ya  [m * 32 + t * 4]) = ya;
        *reinterpret_cast<float4*>(&g_yb  [m * 32 + t * 4]) = yb;
        *reinterpret_cast<float4*>(&g_outa[m * 32 + t * 4]) = ya;  // self-loop init
        *reinterpret_cast<float4*>(&g_outb[m * 32 + t * 4]) = yb;  // self-loop init
    }
}

// ---------------- 9. conv2 scatter, src-sorted (both directions) ------------
// Slots [E1, E1+E2): (u,v) -> ya[u] into outa[v];  [E1+E2, E1+2E2): (v,u) -> yb[v] into outb[u].
__global__ void k_scat2(int E1, int E2) {
    int tid = blockIdx.x * 256 + threadIdx.x;
    int j = tid >> 3, t = tid & 7;
    if (j >= 2 * E2) return;
    int2 sd = g_slot2[E1 + j];
    if (j < E2) {
        float4 y = *reinterpret_cast<const float4*>(&g_ya[sd.x * 32 + t * 4]);
        red_add_v4(&g_outa[sd.y * 32 + t * 4], y);
    } else {
        float4 y = *reinterpret_cast<const float4*>(&g_yb[sd.x * 32 + t * 4]);
        red_add_v4(&g_outb[sd.y * 32 + t * 4], y);
    }
}

// ---------------- 10. final: deferred conv2 scaling + even*odd + dot Wp -----
__global__ void k_final(const int* __restrict__ idx,
                        const float* __restrict__ b2a, const float* __restrict__ b2b,
                        const float* __restrict__ Wp, const float* __restrict__ bp,
                        float* __restrict__ out, int Q)
{
    int tid = blockIdx.x * 256 + threadIdx.x;
    int q = tid >> 3, t = tid & 7;
    bool ok = (q < Q);
    int i0 = 0, i1 = 0;
    if (ok) { i0 = idx[2 * q]; i1 = idx[2 * q + 1]; }

    float f0 = g_dinvf[i0], g0 = g_dinvb[i0];
    float f1 = g_dinvf[i1], g1 = g_dinvb[i1];
    float4 ba = *reinterpret_cast<const float4*>(&b2a[t * 4]);
    float4 bb = *reinterpret_cast<const float4*>(&b2b[t * 4]);

    float4 a0 = *reinterpret_cast<const float4*>(&g_outa[i0 * 32 + t * 4]);
    float4 c0 = *reinterpret_cast<const float4*>(&g_outb[i0 * 32 + t * 4]);
    float4 a1 = *reinterpret_cast<const float4*>(&g_outa[i1 * 32 + t * 4]);
    float4 c1 = *reinterpret_cast<const float4*>(&g_outb[i1 * 32 + t * 4]);

    float4 h0, h1;
    h0.x = fmaxf(a0.x * f0 + ba.x, 0.f) + fmaxf(c0.x * g0 + bb.x, 0.f);
    h0.y = fmaxf(a0.y * f0 + ba.y, 0.f) + fmaxf(c0.y * g0 + bb.y, 0.f);
    h0.z = fmaxf(a0.z * f0 + ba.z, 0.f) + fmaxf(c0.z * g0 + bb.z, 0.f);
    h0.w = fmaxf(a0.w * f0 + ba.w, 0.f) + fmaxf(c0.w * g0 + bb.w, 0.f);
    h1.x = fmaxf(a1.x * f1 + ba.x, 0.f) + fmaxf(c1.x * g1 + bb.x, 0.f);
    h1.y = fmaxf(a1.y * f1 + ba.y, 0.f) + fmaxf(c1.y * g1 + bb.y, 0.f);
    h1.z = fmaxf(a1.z * f1 + ba.z, 0.f) + fmaxf(c1.z * g1 + bb.z, 0.f);
    h1.w = fmaxf(a1.w * f1 + ba.w, 0.f) + fmaxf(c1.w * g1 + bb.w, 0.f);

    float4 wp4 = *reinterpret_cast<const float4*>(&Wp[t * 4]);
    float s = h0.x * h1.x * wp4.x + h0.y * h1.y * wp4.y
            + h0.z * h1.z * wp4.z + h0.w * h1.w * wp4.w;
    s += __shfl_xor_sync(0xffffffffu, s, 1, 8);
    s += __shfl_xor_sync(0xffffffffu, s, 2, 8);
    s += __shfl_xor_sync(0xffffffffu, s, 4, 8);
    if (ok && t == 0) out[q] = s + __ldg(bp);
}

// ---------------- launch ----------------------------------------------------
extern "C" void kernel_launch(void* const* d_in, const int* in_sizes, int n_in,
                              void* d_out, int out_size) {
    const int*   x    = (const int*)  d_in[0];
    const int*   e1   = (const int*)  d_in[1];
    const int*   pos  = (const int*)  d_in[2];
    const int*   idx  = (const int*)  d_in[3];
    const int*   e2   = (const int*)  d_in[4];
    const float* emb  = (const float*)d_in[5];
    const float* W1   = (const float*)d_in[6];
    const float* b1   = (const float*)d_in[7];
    const float* W2a  = (const float*)d_in[8];
    const float* b2a  = (const float*)d_in[9];
    const float* W2b  = (const float*)d_in[10];
    const float* b2b  = (const float*)d_in[11];
    const float* Wp   = (const float*)d_in[12];
    const float* bp   = (const float*)d_in[13];
    float* out = (float*)d_out;

    int n1 = in_sizes[0];
    int E1 = in_sizes[1] / 2;
    int np = in_sizes[2] / 2;
    int Q  = in_sizes[3] / 2;
    int E2 = in_sizes[4] / 2;

    int base_u = n1;
    int base_v = n1 + np;
    int ntot   = n1 + 2 * np;
    int nblk   = (ntot + 1023) / 1024;
    int mx = (np > n1) ? np : n1;
    int Em = (E1 > E2) ? E1 : E2;

    k_zero  <<<(ntot + 255) / 256, 256>>>(ntot, n1);
    k_count <<<(Em + 255) / 256, 256>>>(e1, e2, E1, E2, base_u, base_v);
    k_scanA <<<nblk, 256>>>(ntot);
    k_scanB <<<1, 512>>>(nblk);
    k_scanC <<<(ntot + 255) / 256, 256>>>(ntot);
    k_dinv  <<<(mx + 255) / 256, 256>>>(n1, np, base_u, base_v);
    k_fill  <<<(Em + 255) / 256, 256>>>(e1, e2, E1, E2, base_u, base_v);
    k_embed <<<(n1 + 127) / 128, 256>>>(x, emb, W1, n1);
    k_scat1 <<<(int)(((long long)E1 * 8 + 255) / 256), 256>>>(E1);
    k_pair  <<<(int)(((long long)np * 8 + 255) / 256), 256>>>(pos, W2a, b1, W2b, np);
    k_scat2 <<<(int)(((long long)E2 * 16 + 255) / 256), 256>>>(E1, E2);
    k_final <<<(int)(((long long)Q  * 8 + 255) / 256), 256>>>(idx, b2a, b2b, Wp, bp, out, Q);
}

// round 15
// speedup vs baseline: 1.4974x; 1.4532x over previous
#include <cuda_runtime.h>

// Problem-shape maxima (compile-time array sizing; runtime uses in_sizes)
#define N1MAX 50000
#define NPMAX 200000
#define H2 32

// ---------------- scratch (static __device__, no allocation) ----------------
__device__ int   g_cnt1 [N1MAX];
__device__ int   g_cnt2f[NPMAX];
__device__ int   g_cnt2b[NPMAX];
__device__ float g_dinv1[N1MAX];
__device__ float g_dinvf[NPMAX];
__device__ float g_dinvb[NPMAX];
__device__ __align__(16) float g_y1  [N1MAX * H2];   // xw1 * dinv1[src]
__device__ __align__(16) float g_out1[N1MAX * H2];   // raw acc: y1[d] + sum y1[src]
__device__ __align__(16) float g_ya  [NPMAX * H2];
__device__ __align__(16) float g_yb  [NPMAX * H2];
__device__ __align__(16) float g_outa[NPMAX * H2];
__device__ __align__(16) float g_outb[NPMAX * H2];

__device__ __forceinline__ void red_add_v4(float* addr, float4 v) {
    asm volatile("red.global.add.v4.f32 [%0], {%1,%2,%3,%4};"
                 :: "l"(addr), "f"(v.x), "f"(v.y), "f"(v.z), "f"(v.w)
                 : "memory");
}

// ---------------- 1. zero degree counters ----------------
__global__ void k_zero(int n1, int np) {
    int i = blockIdx.x * blockDim.x + threadIdx.x;
    if (i < np) { g_cnt2f[i] = 0; g_cnt2b[i] = 0; }
    if (i < n1) { g_cnt1[i] = 0; }
}

// ---------------- 2. degree counting (all three graphs in one pass) --------
__global__ void k_count(const int* __restrict__ e1, const int* __restrict__ e2,
                        int E1, int E2) {
    int i = blockIdx.x * blockDim.x + threadIdx.x;
    if (i < E1) atomicAdd(&g_cnt1[e1[E1 + i]], 1);          // conv1 dst = edge1[1]
    if (i < E2) {
        atomicAdd(&g_cnt2f[e2[E2 + i]], 1);                  // conv2a dst = ei2[1]
        atomicAdd(&g_cnt2b[e2[i]],      1);                  // conv2b dst = ei2[0]
    }
}

// ---------------- 3. rsqrt degrees ONCE (deg = count + 1 self-loop) ---------
__global__ void k_dinv(int n1, int np) {
    int i = blockIdx.x * blockDim.x + threadIdx.x;
    if (i < np) {
        g_dinvf[i] = rsqrtf((float)(g_cnt2f[i] + 1));
        g_dinvb[i] = rsqrtf((float)(g_cnt2b[i] + 1));
    }
    if (i < n1) g_dinv1[i] = rsqrtf((float)(g_cnt1[i] + 1));
}

// ---------------- 4. embed gather + register-tiled GEMM (256 -> 32) ---------
__global__ __launch_bounds__(256) void k_embed(
    const int* __restrict__ x, const float* __restrict__ emb,
    const float* __restrict__ W1, int n1)
{
    __shared__ __align__(16) float Ws[64 * 32];       // 8 KB (per-chunk W)
    __shared__ __align__(16) float As[128 * 68];      // 34 KB, row stride 68

    int tid = threadIdx.x;
    int c4 = tid & 7;
    int ty = (tid >> 3) & 7;
    int st = tid >> 6;
    int nodeBase = blockIdx.x * 128;

    float acc[4][4];
    #pragma unroll
    for (int m = 0; m < 4; m++)
        #pragma unroll
        for (int c = 0; c < 4; c++) acc[m][c] = 0.f;

    int lcol = tid & 15;
    int lrow = tid >> 4;

    for (int ch = 0; ch < 4; ch++) {
        #pragma unroll
        for (int i = 0; i < 8; i++)
            Ws[i * 256 + tid] = W1[ch * 2048 + i * 256 + tid];
        #pragma unroll
        for (int pass = 0; pass < 8; pass++) {
            int r = lrow + pass * 16;
            int n = nodeBase + r;
            if (n < n1) {
                int xi = x[n];
                float4 v = reinterpret_cast<const float4*>(emb)
                               [(size_t)xi * 64 + ch * 16 + lcol];
                *reinterpret_cast<float4*>(&As[r * 68 + lcol * 4]) = v;
            }
        }
        __syncthreads();

        #pragma unroll
        for (int k4 = 0; k4 < 16; k4++) {
            float4 w0 = *reinterpret_cast<const float4*>(&Ws[(k4 * 4 + 0) * 32 + c4 * 4]);
            float4 w1 = *reinterpret_cast<const float4*>(&Ws[(k4 * 4 + 1) * 32 + c4 * 4]);
            float4 w2 = *reinterpret_cast<const float4*>(&Ws[(k4 * 4 + 2) * 32 + c4 * 4]);
            float4 w3 = *reinterpret_cast<const float4*>(&Ws[(k4 * 4 + 3) * 32 + c4 * 4]);
            #pragma unroll
            for (int m = 0; m < 4; m++) {
                int row = st * 32 + ty + 8 * m;
                float4 a = *reinterpret_cast<const float4*>(&As[row * 68 + k4 * 4]);
                acc[m][0] += a.x * w0.x + a.y * w1.x + a.z * w2.x + a.w * w3.x;
                acc[m][1] += a.x * w0.y + a.y * w1.y + a.z * w2.y + a.w * w3.y;
                acc[m][2] += a.x * w0.z + a.y * w1.z + a.z * w2.z + a.w * w3.z;
                acc[m][3] += a.x * w0.w + a.y * w1.w + a.z * w2.w + a.w * w3.w;
            }
        }
        __syncthreads();
    }

    #pragma unroll
    for (int m = 0; m < 4; m++) {
        int node = nodeBase + st * 32 + ty + 8 * m;
        if (node < n1) {
            float dv = g_dinv1[node];
            float4 y = make_float4(acc[m][0] * dv, acc[m][1] * dv,
                                   acc[m][2] * dv, acc[m][3] * dv);
            *reinterpret_cast<float4*>(&g_y1  [node * 32 + c4 * 4]) = y;
            *reinterpret_cast<float4*>(&g_out1[node * 32 + c4 * 4]) = y;  // self-loop init
        }
    }
}

// ---------------- 5. conv1 scatter: 4 edges per 8-thread group, MLP=4 -------
// Lane 0 loads int4 src/dst quads, shfl-broadcast; 4 independent read chains.
__global__ void k_scatter1(const int* __restrict__ e1, int E1) {
    int tid = blockIdx.x * 256 + threadIdx.x;
    int j = tid >> 3, t = tid & 7;
    int e0 = j * 4;
    if (e0 >= E1) return;

    int s[4], d[4];
    if (e0 + 4 <= E1 && (E1 & 3) == 0) {
        int4 sv, dv;
        if (t == 0) {
            sv = *reinterpret_cast<const int4*>(e1 + e0);
            dv = *reinterpret_cast<const int4*>(e1 + E1 + e0);
        }
        s[0] = __shfl_sync(0xffffffffu, sv.x, 0, 8);
        s[1] = __shfl_sync(0xffffffffu, sv.y, 0, 8);
        s[2] = __shfl_sync(0xffffffffu, sv.z, 0, 8);
        s[3] = __shfl_sync(0xffffffffu, sv.w, 0, 8);
        d[0] = __shfl_sync(0xffffffffu, dv.x, 0, 8);
        d[1] = __shfl_sync(0xffffffffu, dv.y, 0, 8);
        d[2] = __shfl_sync(0xffffffffu, dv.z, 0, 8);
        d[3] = __shfl_sync(0xffffffffu, dv.w, 0, 8);

        float4 y0 = *reinterpret_cast<const float4*>(&g_y1[s[0] * 32 + t * 4]);
        float4 y1 = *reinterpret_cast<const float4*>(&g_y1[s[1] * 32 + t * 4]);
        float4 y2 = *reinterpret_cast<const float4*>(&g_y1[s[2] * 32 + t * 4]);
        float4 y3 = *reinterpret_cast<const float4*>(&g_y1[s[3] * 32 + t * 4]);
        red_add_v4(&g_out1[d[0] * 32 + t * 4], y0);
        red_add_v4(&g_out1[d[1] * 32 + t * 4], y1);
        red_add_v4(&g_out1[d[2] * 32 + t * 4], y2);
        red_add_v4(&g_out1[d[3] * 32 + t * 4], y3);
    } else {
        #pragma unroll
        for (int k = 0; k < 4; k++) {
            int e = e0 + k;
            if (e < E1) {
                int ss = e1[e], dd = e1[E1 + e];
                float4 y = *reinterpret_cast<const float4*>(&g_y1[ss * 32 + t * 4]);
                red_add_v4(&g_out1[dd * 32 + t * 4], y);
            }
        }
    }
}

// ---------------- 6. pair gather-multiply + fused 32x32 GEMVs ---------------
// Applies conv1's deferred dst scaling: h = relu(acc * dinv1 + b1).
__global__ __launch_bounds__(256) void k_pair(
    const int* __restrict__ pos,
    const float* __restrict__ W2a, const float* __restrict__ b1v,
    const float* __restrict__ W2b, int np)
{
    __shared__ __align__(16) float Was[1024];
    __shared__ __align__(16) float Wbs[1024];
    int tid = threadIdx.x;
    for (int i = tid; i < 1024; i += 256) { Was[i] = W2a[i]; Wbs[i] = W2b[i]; }
    __syncthreads();

    int g = blockIdx.x * 256 + tid;
    int m = g >> 3, t = g & 7;
    bool ok = (m < np);
    int p0 = 0, p1 = 0;
    if (ok) { p0 = pos[2 * m]; p1 = pos[2 * m + 1]; }

    float dv0 = g_dinv1[p0], dv1 = g_dinv1[p1];
    float4 b14 = *reinterpret_cast<const float4*>(&b1v[t * 4]);
    float4 h0 = *reinterpret_cast<const float4*>(&g_out1[p0 * 32 + t * 4]);
    float4 h1 = *reinterpret_cast<const float4*>(&g_out1[p1 * 32 + t * 4]);
    float4 hp;
    hp.x = fmaxf(h0.x * dv0 + b14.x, 0.f) * fmaxf(h1.x * dv1 + b14.x, 0.f);
    hp.y = fmaxf(h0.y * dv0 + b14.y, 0.f) * fmaxf(h1.y * dv1 + b14.y, 0.f);
    hp.z = fmaxf(h0.z * dv0 + b14.z, 0.f) * fmaxf(h1.z * dv1 + b14.z, 0.f);
    hp.w = fmaxf(h0.w * dv0 + b14.w, 0.f) * fmaxf(h1.w * dv1 + b14.w, 0.f);

    float4 aa = make_float4(0.f, 0.f, 0.f, 0.f);
    float4 ab = make_float4(0.f, 0.f, 0.f, 0.f);
    #pragma unroll
    for (int src = 0; src < 8; src++) {
        float hv[4];
        hv[0] = __shfl_sync(0xffffffffu, hp.x, src, 8);
        hv[1] = __shfl_sync(0xffffffffu, hp.y, src, 8);
        hv[2] = __shfl_sync(0xffffffffu, hp.z, src, 8);
        hv[3] = __shfl_sync(0xffffffffu, hp.w, src, 8);
        #pragma unroll
        for (int kk = 0; kk < 4; kk++) {
            int k = src * 4 + kk;
            float4 wa = *reinterpret_cast<const float4*>(&Was[k * 32 + t * 4]);
            float4 wb = *reinterpret_cast<const float4*>(&Wbs[k * 32 + t * 4]);
            aa.x += hv[kk] * wa.x; aa.y += hv[kk] * wa.y;
            aa.z += hv[kk] * wa.z; aa.w += hv[kk] * wa.w;
            ab.x += hv[kk] * wb.x; ab.y += hv[kk] * wb.y;
            ab.z += hv[kk] * wb.z; ab.w += hv[kk] * wb.w;
        }
    }

    if (ok) {
        float da = g_dinvf[m], db = g_dinvb[m];
        float4 ya = make_float4(aa.x * da, aa.y * da, aa.z * da, aa.w * da);
        float4 yb = make_float4(ab.x * db, ab.y * db, ab.z * db, ab.w * db);
        *reinterpret_cast<float4*>(&g_ya  [m * 32 + t * 4]) = ya;
        *reinterpret_cast<float4*>(&g_yb  [m * 32 + t * 4]) = yb;
        *reinterpret_cast<float4*>(&g_outa[m * 32 + t * 4]) = ya;  // self-loop init
        *reinterpret_cast<float4*>(&g_outb[m * 32 + t * 4]) = yb;  // self-loop init
    }
}

// ---------------- 7. conv2 scatter: 4 edges/group, both dirs, MLP=8 ---------
__global__ void k_scatter2(const int* __restrict__ e2, int E2) {
    int tid = blockIdx.x * 256 + threadIdx.x;
    int j = tid >> 3, t = tid & 7;
    int e0 = j * 4;
    if (e0 >= E2) return;

    if (e0 + 4 <= E2 && (E2 & 3) == 0) {
        int4 uv, vv;
        if (t == 0) {
            uv = *reinterpret_cast<const int4*>(e2 + e0);
            vv = *reinterpret_cast<const int4*>(e2 + E2 + e0);
        }
        int u[4], v[4];
        u[0] = __shfl_sync(0xffffffffu, uv.x, 0, 8);
        u[1] = __shfl_sync(0xffffffffu, uv.y, 0, 8);
        u[2] = __shfl_sync(0xffffffffu, uv.z, 0, 8);
        u[3] = __shfl_sync(0xffffffffu, uv.w, 0, 8);
        v[0] = __shfl_sync(0xffffffffu, vv.x, 0, 8);
        v[1] = __shfl_sync(0xffffffffu, vv.y, 0, 8);
        v[2] = __shfl_sync(0xffffffffu, vv.z, 0, 8);
        v[3] = __shfl_sync(0xffffffffu, vv.w, 0, 8);

        float4 a0 = *reinterpret_cast<const float4*>(&g_ya[u[0] * 32 + t * 4]);
        float4 a1 = *reinterpret_cast<const float4*>(&g_ya[u[1] * 32 + t * 4]);
        float4 a2 = *reinterpret_cast<const float4*>(&g_ya[u[2] * 32 + t * 4]);
        float4 a3 = *reinterpret_cast<const float4*>(&g_ya[u[3] * 32 + t * 4]);
        float4 b0 = *reinterpret_cast<const float4*>(&g_yb[v[0] * 32 + t * 4]);
        float4 b1 = *reinterpret_cast<const float4*>(&g_yb[v[1] * 32 + t * 4]);
        float4 b2 = *reinterpret_cast<const float4*>(&g_yb[v[2] * 32 + t * 4]);
        float4 b3 = *reinterpret_cast<const float4*>(&g_yb[v[3] * 32 + t * 4]);
        red_add_v4(&g_outa[v[0] * 32 + t * 4], a0);
        red_add_v4(&g_outa[v[1] * 32 + t * 4], a1);
        red_add_v4(&g_outa[v[2] * 32 + t * 4], a2);
        red_add_v4(&g_outa[v[3] * 32 + t * 4], a3);
        red_add_v4(&g_outb[u[0] * 32 + t * 4], b0);
        red_add_v4(&g_outb[u[1] * 32 + t * 4], b1);
        red_add_v4(&g_outb[u[2] * 32 + t * 4], b2);
        red_add_v4(&g_outb[u[3] * 32 + t * 4], b3);
    } else {
        #pragma unroll
        for (int k = 0; k < 4; k++) {
            int e = e0 + k;
            if (e < E2) {
                int uu = e2[e], vv2 = e2[E2 + e];
                float4 a = *reinterpret_cast<const float4*>(&g_ya[uu * 32 + t * 4]);
                red_add_v4(&g_outa[vv2 * 32 + t * 4], a);
                float4 b = *reinterpret_cast<const float4*>(&g_yb[vv2 * 32 + t * 4]);
                red_add_v4(&g_outb[uu * 32 + t * 4], b);
            }
        }
    }
}

// ---------------- 8. final: deferred conv2 scaling + even*odd + dot Wp ------
__global__ void k_final(const int* __restrict__ idx,
                        const float* __restrict__ b2a, const float* __restrict__ b2b,
                        const float* __restrict__ Wp, const float* __restrict__ bp,
                        float* __restrict__ out, int Q)
{
    int tid = blockIdx.x * 256 + threadIdx.x;
    int q = tid >> 3, t = tid & 7;
    bool ok = (q < Q);
    int i0 = 0, i1 = 0;
    if (ok) { i0 = idx[2 * q]; i1 = idx[2 * q + 1]; }

    float f0 = g_dinvf[i0], g0 = g_dinvb[i0];
    float f1 = g_dinvf[i1], g1 = g_dinvb[i1];
    float4 ba = *reinterpret_cast<const float4*>(&b2a[t * 4]);
    float4 bb = *reinterpret_cast<const float4*>(&b2b[t * 4]);

    float4 a0 = *reinterpret_cast<const float4*>(&g_outa[i0 * 32 + t * 4]);
    float4 c0 = *reinterpret_cast<const float4*>(&g_outb[i0 * 32 + t * 4]);
    float4 a1 = *reinterpret_cast<const float4*>(&g_outa[i1 * 32 + t * 4]);
    float4 c1 = *reinterpret_cast<const float4*>(&g_outb[i1 * 32 + t * 4]);

    float4 h0, h1;
    h0.x = fmaxf(a0.x * f0 + ba.x, 0.f) + fmaxf(c0.x * g0 + bb.x, 0.f);
    h0.y = fmaxf(a0.y * f0 + ba.y, 0.f) + fmaxf(c0.y * g0 + bb.y, 0.f);
    h0.z = fmaxf(a0.z * f0 + ba.z, 0.f) + fmaxf(c0.z * g0 + bb.z, 0.f);
    h0.w = fmaxf(a0.w * f0 + ba.w, 0.f) + fmaxf(c0.w * g0 + bb.w, 0.f);
    h1.x = fmaxf(a1.x * f1 + ba.x, 0.f) + fmaxf(c1.x * g1 + bb.x, 0.f);
    h1.y = fmaxf(a1.y * f1 + ba.y, 0.f) + fmaxf(c1.y * g1 + bb.y, 0.f);
    h1.z = fmaxf(a1.z * f1 + ba.z, 0.f) + fmaxf(c1.z * g1 + bb.z, 0.f);
    h1.w = fmaxf(a1.w * f1 + ba.w, 0.f) + fmaxf(c1.w * g1 + bb.w, 0.f);

    float4 wp4 = *reinterpret_cast<const float4*>(&Wp[t * 4]);
    float s = h0.x * h1.x * wp4.x + h0.y * h1.y * wp4.y
            + h0.z * h1.z * wp4.z + h0.w * h1.w * wp4.w;
    s += __shfl_xor_sync(0xffffffffu, s, 1, 8);
    s += __shfl_xor_sync(0xffffffffu, s, 2, 8);
    s += __shfl_xor_sync(0xffffffffu, s, 4, 8);
    if (ok && t == 0) out[q] = s + __ldg(bp);
}

// ---------------- launch ----------------------------------------------------
extern "C" void kernel_launch(void* const* d_in, const int* in_sizes, int n_in,
                              void* d_out, int out_size) {
    const int*   x    = (const int*)  d_in[0];
    const int*   e1   = (const int*)  d_in[1];
    const int*   pos  = (const int*)  d_in[2];
    const int*   idx  = (const int*)  d_in[3];
    const int*   e2   = (const int*)  d_in[4];
    const float* emb  = (const float*)d_in[5];
    const float* W1   = (const float*)d_in[6];
    const float* b1   = (const float*)d_in[7];
    const float* W2a  = (const float*)d_in[8];
    const float* b2a  = (const float*)d_in[9];
    const float* W2b  = (const float*)d_in[10];
    const float* b2b  = (const float*)d_in[11];
    const float* Wp   = (const float*)d_in[12];
    const float* bp   = (const float*)d_in[13];
    float* out = (float*)d_out;

    int n1 = in_sizes[0];
    int E1 = in_sizes[1] / 2;
    int np = in_sizes[2] / 2;
    int Q  = in_sizes[3] / 2;
    int E2 = in_sizes[4] / 2;

    int mx = (np > n1) ? np : n1;
    int Em = (E1 > E2) ? E1 : E2;

    long long g1t = ((long long)((E1 + 3) / 4)) * 8;   // threads for scatter1
    long long g2t = ((long long)((E2 + 3) / 4)) * 8;   // threads for scatter2

    k_zero    <<<(mx + 255) / 256, 256>>>(n1, np);
    k_count   <<<(Em + 255) / 256, 256>>>(e1, e2, E1, E2);
    k_dinv    <<<(mx + 255) / 256, 256>>>(n1, np);
    k_embed   <<<(n1 + 127) / 128, 256>>>(x, emb, W1, n1);
    k_scatter1<<<(int)((g1t + 255) / 256), 256>>>(e1, E1);
    k_pair    <<<(int)(((long long)np * 8 + 255) / 256), 256>>>(pos, W2a, b1, W2b, np);
    k_scatter2<<<(int)((g2t + 255) / 256), 256>>>(e2, E2);
    k_final   <<<(int)(((long long)Q  * 8 + 255) / 256), 256>>>(idx, b2a, b2b, Wp, bp, out, Q);
}

// round 16
// speedup vs baseline: 1.5983x; 1.0674x over previous
#include <cuda_runtime.h>

// Problem-shape maxima (compile-time array sizing; runtime uses in_sizes)
#define N1MAX 50000
#define NPMAX 200000
#define H2 32

// ---------------- scratch (static __device__, no allocation) ----------------
__device__ int   g_cnt1 [N1MAX];
__device__ int   g_cnt2f[NPMAX];
__device__ int   g_cnt2b[NPMAX];
__device__ float g_dinv1[N1MAX];
__device__ float g_dinvf[NPMAX];
__device__ float g_dinvb[NPMAX];
__device__ __align__(16) float g_y1  [N1MAX * H2];   // embed: raw xw; after k_scale: xw*dinv1
__device__ __align__(16) float g_out1[N1MAX * H2];   // raw acc: y1[d] + sum y1[src]
__device__ __align__(16) float g_ya  [NPMAX * H2];
__device__ __align__(16) float g_yb  [NPMAX * H2];
__device__ __align__(16) float g_outa[NPMAX * H2];
__device__ __align__(16) float g_outb[NPMAX * H2];

__device__ __forceinline__ void red_add_v4(float* addr, float4 v) {
    asm volatile("red.global.add.v4.f32 [%0], {%1,%2,%3,%4};"
                 :: "l"(addr), "f"(v.x), "f"(v.y), "f"(v.z), "f"(v.w)
                 : "memory");
}

// ---------------- 1. zero degree counters ----------------
__global__ void k_zero(int n1, int np) {
    int i = blockIdx.x * blockDim.x + threadIdx.x;
    if (i < np) { g_cnt2f[i] = 0; g_cnt2b[i] = 0; }
    if (i < n1) { g_cnt1[i] = 0; }
}

// ---------------- 2. degree counting, 4 edges/thread via int4 --------------
__global__ void k_count(const int* __restrict__ e1, const int* __restrict__ e2,
                        int E1, int E2) {
    int i = blockIdx.x * blockDim.x + threadIdx.x;
    int e0 = i * 4;
    if (e0 < E1) {
        if (e0 + 4 <= E1 && (E1 & 3) == 0) {
            int4 d = *reinterpret_cast<const int4*>(e1 + E1 + e0);
            atomicAdd(&g_cnt1[d.x], 1); atomicAdd(&g_cnt1[d.y], 1);
            atomicAdd(&g_cnt1[d.z], 1); atomicAdd(&g_cnt1[d.w], 1);
        } else {
            for (int k = 0; k < 4 && e0 + k < E1; k++)
                atomicAdd(&g_cnt1[e1[E1 + e0 + k]], 1);
        }
    }
    if (e0 < E2) {
        if (e0 + 4 <= E2 && (E2 & 3) == 0) {
            int4 u = *reinterpret_cast<const int4*>(e2 + e0);
            int4 v = *reinterpret_cast<const int4*>(e2 + E2 + e0);
            atomicAdd(&g_cnt2f[v.x], 1); atomicAdd(&g_cnt2f[v.y], 1);
            atomicAdd(&g_cnt2f[v.z], 1); atomicAdd(&g_cnt2f[v.w], 1);
            atomicAdd(&g_cnt2b[u.x], 1); atomicAdd(&g_cnt2b[u.y], 1);
            atomicAdd(&g_cnt2b[u.z], 1); atomicAdd(&g_cnt2b[u.w], 1);
        } else {
            for (int k = 0; k < 4 && e0 + k < E2; k++) {
                atomicAdd(&g_cnt2f[e2[E2 + e0 + k]], 1);
                atomicAdd(&g_cnt2b[e2[e0 + k]],      1);
            }
        }
    }
}

// ---------------- 3. rsqrt degrees ONCE (deg = count + 1 self-loop) ---------
__global__ void k_dinv(int n1, int np) {
    int i = blockIdx.x * blockDim.x + threadIdx.x;
    if (i < np) {
        g_dinvf[i] = rsqrtf((float)(g_cnt2f[i] + 1));
        g_dinvb[i] = rsqrtf((float)(g_cnt2b[i] + 1));
    }
    if (i < n1) g_dinv1[i] = rsqrtf((float)(g_cnt1[i] + 1));
}

// ---------------- 4. embed gather + register-tiled GEMM: RAW xw only --------
// No dinv dependency -> runs concurrently with zero/count/dinv on stream s1.
__global__ __launch_bounds__(256) void k_embed(
    const int* __restrict__ x, const float* __restrict__ emb,
    const float* __restrict__ W1, int n1)
{
    __shared__ __align__(16) float Ws[64 * 32];       // 8 KB (per-chunk W)
    __shared__ __align__(16) float As[128 * 68];      // 34 KB, row stride 68

    int tid = threadIdx.x;
    int c4 = tid & 7;
    int ty = (tid >> 3) & 7;
    int st = tid >> 6;
    int nodeBase = blockIdx.x * 128;

    float acc[4][4];
    #pragma unroll
    for (int m = 0; m < 4; m++)
        #pragma unroll
        for (int c = 0; c < 4; c++) acc[m][c] = 0.f;

    int lcol = tid & 15;
    int lrow = tid >> 4;

    for (int ch = 0; ch < 4; ch++) {
        #pragma unroll
        for (int i = 0; i < 8; i++)
            Ws[i * 256 + tid] = W1[ch * 2048 + i * 256 + tid];
        #pragma unroll
        for (int pass = 0; pass < 8; pass++) {
            int r = lrow + pass * 16;
            int n = nodeBase + r;
            if (n < n1) {
                int xi = x[n];
                float4 v = reinterpret_cast<const float4*>(emb)
                               [(size_t)xi * 64 + ch * 16 + lcol];
                *reinterpret_cast<float4*>(&As[r * 68 + lcol * 4]) = v;
            }
        }
        __syncthreads();

        #pragma unroll
        for (int k4 = 0; k4 < 16; k4++) {
            float4 w0 = *reinterpret_cast<const float4*>(&Ws[(k4 * 4 + 0) * 32 + c4 * 4]);
            float4 w1 = *reinterpret_cast<const float4*>(&Ws[(k4 * 4 + 1) * 32 + c4 * 4]);
            float4 w2 = *reinterpret_cast<const float4*>(&Ws[(k4 * 4 + 2) * 32 + c4 * 4]);
            float4 w3 = *reinterpret_cast<const float4*>(&Ws[(k4 * 4 + 3) * 32 + c4 * 4]);
            #pragma unroll
            for (int m = 0; m < 4; m++) {
                int row = st * 32 + ty + 8 * m;
                float4 a = *reinterpret_cast<const float4*>(&As[row * 68 + k4 * 4]);
                acc[m][0] += a.x * w0.x + a.y * w1.x + a.z * w2.x + a.w * w3.x;
                acc[m][1] += a.x * w0.y + a.y * w1.y + a.z * w2.y + a.w * w3.y;
                acc[m][2] += a.x * w0.z + a.y * w1.z + a.z * w2.z + a.w * w3.z;
                acc[m][3] += a.x * w0.w + a.y * w1.w + a.z * w2.w + a.w * w3.w;
            }
        }
        __syncthreads();
    }

    #pragma unroll
    for (int m = 0; m < 4; m++) {
        int node = nodeBase + st * 32 + ty + 8 * m;
        if (node < n1) {
            *reinterpret_cast<float4*>(&g_y1[node * 32 + c4 * 4]) =
                make_float4(acc[m][0], acc[m][1], acc[m][2], acc[m][3]);
        }
    }
}

// ---------------- 5. scale: y1 = xw*dinv1 (in place), out1 = y1 -------------
__global__ void k_scale(int n1) {
    int i = blockIdx.x * 256 + threadIdx.x;
    int node = i >> 3, t = i & 7;
    if (node >= n1) return;
    float dv = g_dinv1[node];
    float4 v = *reinterpret_cast<const float4*>(&g_y1[node * 32 + t * 4]);
    v.x *= dv; v.y *= dv; v.z *= dv; v.w *= dv;
    *reinterpret_cast<float4*>(&g_y1  [node * 32 + t * 4]) = v;
    *reinterpret_cast<float4*>(&g_out1[node * 32 + t * 4]) = v;   // self-loop init
}

// ---------------- 6. conv1 scatter: 8 edges per 8-thread group, MLP=8 -------
// Uniform int4 index loads (L1 broadcast within the group), independent chains.
__global__ void k_scatter1(const int* __restrict__ e1, int E1) {
    int tid = blockIdx.x * 256 + threadIdx.x;
    int j = tid >> 3, t = tid & 7;
    int e0 = j * 8;
    if (e0 >= E1) return;

    if (e0 + 8 <= E1 && (E1 & 3) == 0) {
        int4 s0 = *reinterpret_cast<const int4*>(e1 + e0);
        int4 s1 = *reinterpret_cast<const int4*>(e1 + e0 + 4);
        int4 d0 = *reinterpret_cast<const int4*>(e1 + E1 + e0);
        int4 d1 = *reinterpret_cast<const int4*>(e1 + E1 + e0 + 4);
        int s[8] = {s0.x, s0.y, s0.z, s0.w, s1.x, s1.y, s1.z, s1.w};
        int d[8] = {d0.x, d0.y, d0.z, d0.w, d1.x, d1.y, d1.z, d1.w};
        float4 y[8];
        #pragma unroll
        for (int k = 0; k < 8; k++)
            y[k] = *reinterpret_cast<const float4*>(&g_y1[s[k] * 32 + t * 4]);
        #pragma unroll
        for (int k = 0; k < 8; k++)
            red_add_v4(&g_out1[d[k] * 32 + t * 4], y[k]);
    } else {
        for (int k = 0; k < 8; k++) {
            int e = e0 + k;
            if (e < E1) {
                int ss = e1[e], dd = e1[E1 + e];
                float4 y = *reinterpret_cast<const float4*>(&g_y1[ss * 32 + t * 4]);
                red_add_v4(&g_out1[dd * 32 + t * 4], y);
            }
        }
    }
}

// ---------------- 7. pair gather-multiply + fused 32x32 GEMVs ---------------
// Applies conv1's deferred dst scaling: h = relu(acc * dinv1 + b1).
__global__ __launch_bounds__(256) void k_pair(
    const int* __restrict__ pos,
    const float* __restrict__ W2a, const float* __restrict__ b1v,
    const float* __restrict__ W2b, int np)
{
    __shared__ __align__(16) float Was[1024];
    __shared__ __align__(16) float Wbs[1024];
    int tid = threadIdx.x;
    for (int i = tid; i < 1024; i += 256) { Was[i] = W2a[i]; Wbs[i] = W2b[i]; }
    __syncthreads();

    int g = blockIdx.x * 256 + tid;
    int m = g >> 3, t = g & 7;
    bool ok = (m < np);
    int p0 = 0, p1 = 0;
    if (ok) { p0 = pos[2 * m]; p1 = pos[2 * m + 1]; }

    float dv0 = g_dinv1[p0], dv1 = g_dinv1[p1];
    float4 b14 = *reinterpret_cast<const float4*>(&b1v[t * 4]);
    float4 h0 = *reinterpret_cast<const float4*>(&g_out1[p0 * 32 + t * 4]);
    float4 h1 = *reinterpret_cast<const float4*>(&g_out1[p1 * 32 + t * 4]);
    float4 hp;
    hp.x = fmaxf(h0.x * dv0 + b14.x, 0.f) * fmaxf(h1.x * dv1 + b14.x, 0.f);
    hp.y = fmaxf(h0.y * dv0 + b14.y, 0.f) * fmaxf(h1.y * dv1 + b14.y, 0.f);
    hp.z = fmaxf(h0.z * dv0 + b14.z, 0.f) * fmaxf(h1.z * dv1 + b14.z, 0.f);
    hp.w = fmaxf(h0.w * dv0 + b14.w, 0.f) * fmaxf(h1.w * dv1 + b14.w, 0.f);

    float4 aa = make_float4(0.f, 0.f, 0.f, 0.f);
    float4 ab = make_float4(0.f, 0.f, 0.f, 0.f);
    #pragma unroll
    for (int src = 0; src < 8; src++) {
        float hv[4];
        hv[0] = __shfl_sync(0xffffffffu, hp.x, src, 8);
        hv[1] = __shfl_sync(0xffffffffu, hp.y, src, 8);
        hv[2] = __shfl_sync(0xffffffffu, hp.z, src, 8);
        hv[3] = __shfl_sync(0xffffffffu, hp.w, src, 8);
        #pragma unroll
        for (int kk = 0; kk < 4; kk++) {
            int k = src * 4 + kk;
            float4 wa = *reinterpret_cast<const float4*>(&Was[k * 32 + t * 4]);
            float4 wb = *reinterpret_cast<const float4*>(&Wbs[k * 32 + t * 4]);
            aa.x += hv[kk] * wa.x; aa.y += hv[kk] * wa.y;
            aa.z += hv[kk] * wa.z; aa.w += hv[kk] * wa.w;
            ab.x += hv[kk] * wb.x; ab.y += hv[kk] * wb.y;
            ab.z += hv[kk] * wb.z; ab.w += hv[kk] * wb.w;
        }
    }

    if (ok) {
        float da = g_dinvf[m], db = g_dinvb[m];
        float4 ya = make_float4(aa.x * da, aa.y * da, aa.z * da, aa.w * da);
        float4 yb = make_float4(ab.x * db, ab.y * db, ab.z * db, ab.w * db);
        *reinterpret_cast<float4*>(&g_ya  [m * 32 + t * 4]) = ya;
        *reinterpret_cast<float4*>(&g_yb  [m * 32 + t * 4]) = yb;
        *reinterpret_cast<float4*>(&g_outa[m * 32 + t * 4]) = ya;  // self-loop init
        *reinterpret_cast<float4*>(&g_outb[m * 32 + t * 4]) = yb;  // self-loop init
    }
}

// ---------------- 8. conv2 scatter: 8 edges/group, two phases, MLP=8 --------
__global__ void k_scatter2(const int* __restrict__ e2, int E2) {
    int tid = blockIdx.x * 256 + threadIdx.x;
    int j = tid >> 3, t = tid & 7;
    int e0 = j * 8;
    if (e0 >= E2) return;

    if (e0 + 8 <= E2 && (E2 & 3) == 0) {
        int4 u0 = *reinterpret_cast<const int4*>(e2 + e0);
        int4 u1 = *reinterpret_cast<const int4*>(e2 + e0 + 4);
        int4 v0 = *reinterpret_cast<const int4*>(e2 + E2 + e0);
        int4 v1 = *reinterpret_cast<const int4*>(e2 + E2 + e0 + 4);
        int u[8] = {u0.x, u0.y, u0.z, u0.w, u1.x, u1.y, u1.z, u1.w};
        int v[8] = {v0.x, v0.y, v0.z, v0.w, v1.x, v1.y, v1.z, v1.w};
        float4 y[8];
        #pragma unroll
        for (int k = 0; k < 8; k++)
            y[k] = *reinterpret_cast<const float4*>(&g_ya[u[k] * 32 + t * 4]);
        #pragma unroll
        for (int k = 0; k < 8; k++)
            red_add_v4(&g_outa[v[k] * 32 + t * 4], y[k]);
        #pragma unroll
        for (int k = 0; k < 8; k++)
            y[k] = *reinterpret_cast<const float4*>(&g_yb[v[k] * 32 + t * 4]);
        #pragma unroll
        for (int k = 0; k < 8; k++)
            red_add_v4(&g_outb[u[k] * 32 + t * 4], y[k]);
    } else {
        for (int k = 0; k < 8; k++) {
            int e = e0 + k;
            if (e < E2) {
                int uu = e2[e], vv = e2[E2 + e];
                float4 a = *reinterpret_cast<const float4*>(&g_ya[uu * 32 + t * 4]);
                red_add_v4(&g_outa[vv * 32 + t * 4], a);
                float4 b = *reinterpret_cast<const float4*>(&g_yb[vv * 32 + t * 4]);
                red_add_v4(&g_outb[uu * 32 + t * 4], b);
            }
        }
    }
}

// ---------------- 9. final: deferred conv2 scaling + even*odd + dot Wp ------
__global__ void k_final(const int* __restrict__ idx,
                        const float* __restrict__ b2a, const float* __restrict__ b2b,
                        const float* __restrict__ Wp, const float* __restrict__ bp,
                        float* __restrict__ out, int Q)
{
    int tid = blockIdx.x * 256 + threadIdx.x;
    int q = tid >> 3, t = tid & 7;
    bool ok = (q < Q);
    int i0 = 0, i1 = 0;
    if (ok) { i0 = idx[2 * q]; i1 = idx[2 * q + 1]; }

    float f0 = g_dinvf[i0], g0 = g_dinvb[i0];
    float f1 = g_dinvf[i1], g1 = g_dinvb[i1];
    float4 ba = *reinterpret_cast<const float4*>(&b2a[t * 4]);
    float4 bb = *reinterpret_cast<const float4*>(&b2b[t * 4]);

    float4 a0 = *reinterpret_cast<const float4*>(&g_outa[i0 * 32 + t * 4]);
    float4 c0 = *reinterpret_cast<const float4*>(&g_outb[i0 * 32 + t * 4]);
    float4 a1 = *reinterpret_cast<const float4*>(&g_outa[i1 * 32 + t * 4]);
    float4 c1 = *reinterpret_cast<const float4*>(&g_outb[i1 * 32 + t * 4]);

    float4 h0, h1;
    h0.x = fmaxf(a0.x * f0 + ba.x, 0.f) + fmaxf(c0.x * g0 + bb.x, 0.f);
    h0.y = fmaxf(a0.y * f0 + ba.y, 0.f) + fmaxf(c0.y * g0 + bb.y, 0.f);
    h0.z = fmaxf(a0.z * f0 + ba.z, 0.f) + fmaxf(c0.z * g0 + bb.z, 0.f);
    h0.w = fmaxf(a0.w * f0 + ba.w, 0.f) + fmaxf(c0.w * g0 + bb.w, 0.f);
    h1.x = fmaxf(a1.x * f1 + ba.x, 0.f) + fmaxf(c1.x * g1 + bb.x, 0.f);
    h1.y = fmaxf(a1.y * f1 + ba.y, 0.f) + fmaxf(c1.y * g1 + bb.y, 0.f);
    h1.z = fmaxf(a1.z * f1 + ba.z, 0.f) + fmaxf(c1.z * g1 + bb.z, 0.f);
    h1.w = fmaxf(a1.w * f1 + ba.w, 0.f) + fmaxf(c1.w * g1 + bb.w, 0.f);

    float4 wp4 = *reinterpret_cast<const float4*>(&Wp[t * 4]);
    float s = h0.x * h1.x * wp4.x + h0.y * h1.y * wp4.y
            + h0.z * h1.z * wp4.z + h0.w * h1.w * wp4.w;
    s += __shfl_xor_sync(0xffffffffu, s, 1, 8);
    s += __shfl_xor_sync(0xffffffffu, s, 2, 8);
    s += __shfl_xor_sync(0xffffffffu, s, 4, 8);
    if (ok && t == 0) out[q] = s + __ldg(bp);
}

// ---------------- launch: forked graph (embed || degree pipeline) -----------
extern "C" void kernel_launch(void* const* d_in, const int* in_sizes, int n_in,
                              void* d_out, int out_size) {
    const int*   x    = (const int*)  d_in[0];
    const int*   e1   = (const int*)  d_in[1];
    const int*   pos  = (const int*)  d_in[2];
    const int*   idx  = (const int*)  d_in[3];
    const int*   e2   = (const int*)  d_in[4];
    const float* emb  = (const float*)d_in[5];
    const float* W1   = (const float*)d_in[6];
    const float* b1   = (const float*)d_in[7];
    const float* W2a  = (const float*)d_in[8];
    const float* b2a  = (const float*)d_in[9];
    const float* W2b  = (const float*)d_in[10];
    const float* b2b  = (const float*)d_in[11];
    const float* Wp   = (const float*)d_in[12];
    const float* bp   = (const float*)d_in[13];
    float* out = (float*)d_out;

    int n1 = in_sizes[0];
    int E1 = in_sizes[1] / 2;
    int np = in_sizes[2] / 2;
    int Q  = in_sizes[3] / 2;
    int E2 = in_sizes[4] / 2;

    int mx = (np > n1) ? np : n1;
    int Em = (E1 > E2) ? E1 : E2;

    long long g1t = ((long long)((E1 + 7) / 8)) * 8;   // threads for scatter1
    long long g2t = ((long long)((E2 + 7) / 8)) * 8;   // threads for scatter2

    // Fork: embed (raw xw, no dinv dependency) runs concurrently with the
    // degree pipeline. Streams/events created per call, never destroyed
    // (kernel_launch is called only a handful of times; host-side objects).
    cudaStream_t s1;
    cudaStreamCreateWithFlags(&s1, cudaStreamNonBlocking);
    cudaEvent_t evFork, evJoin;
    cudaEventCreateWithFlags(&evFork, cudaEventDisableTiming);
    cudaEventCreateWithFlags(&evJoin, cudaEventDisableTiming);

    cudaEventRecord(evFork, 0);
    cudaStreamWaitEvent(s1, evFork, 0);
    k_embed<<<(n1 + 127) / 128, 256, 0, s1>>>(x, emb, W1, n1);
    cudaEventRecord(evJoin, s1);

    k_zero <<<(mx + 255) / 256, 256>>>(n1, np);
    k_count<<<((Em + 3) / 4 + 255) / 256, 256>>>(e1, e2, E1, E2);
    k_dinv <<<(mx + 255) / 256, 256>>>(n1, np);

    cudaStreamWaitEvent(0, evJoin, 0);                 // join embed branch
    k_scale   <<<(int)(((long long)n1 * 8 + 255) / 256), 256>>>(n1);
    k_scatter1<<<(int)((g1t + 255) / 256), 256>>>(e1, E1);
    k_pair    <<<(int)(((long long)np * 8 + 255) / 256), 256>>>(pos, W2a, b1, W2b, np);
    k_scatter2<<<(int)((g2t + 255) / 256), 256>>>(e2, E2);
    k_final   <<<(int)(((long long)Q  * 8 + 255) / 256), 256>>>(idx, b2a, b2b, Wp, bp, out, Q);
}